// round 2
// baseline (speedup 1.0000x reference)
#include <cuda_runtime.h>
#include <math_constants.h>

// Problem constants
#define BATCH 4
#define SEQ   2048
#define DIM   1024
#define DIM3  3072
#define NEGV  (-1e20f)

// Scratch (device globals: allocation-free per harness rules)
__device__ float g_qkv[(long long)BATCH * SEQ * DIM3];      // 96 MB
__device__ float g_scores[(long long)BATCH * SEQ * SEQ];    // 64 MB
__device__ float g_ctx[(long long)BATCH * SEQ * DIM];       // 32 MB

#define TILE 128
#define BK   8

// C = A(MxK, lda) * B(KxN, ldb) [+ bias], batched via strides.
__global__ __launch_bounds__(256) void gemm_nn(
    const float* __restrict__ A, const float* __restrict__ B,
    const float* __restrict__ bias, float* __restrict__ C,
    int M, int N, int K, int lda, int ldb, int ldc,
    long long sA, long long sB, long long sC)
{
    int b = blockIdx.z;
    A += (long long)b * sA; B += (long long)b * sB; C += (long long)b * sC;

    __shared__ float As[BK][TILE];
    __shared__ float Bs[BK][TILE];

    int tid = threadIdx.x;
    int tx = tid & 15, ty = tid >> 4;
    int row0 = blockIdx.y * TILE;
    int col0 = blockIdx.x * TILE;

    float acc[8][8];
    #pragma unroll
    for (int i = 0; i < 8; i++)
        #pragma unroll
        for (int j = 0; j < 8; j++) acc[i][j] = 0.0f;

    for (int k0 = 0; k0 < K; k0 += BK) {
        #pragma unroll
        for (int i = 0; i < 4; i++) {
            int e = tid + i * 256;
            int r = e >> 3, c = e & 7;               // 128 rows x 8 cols of A
            As[c][r] = A[(long long)(row0 + r) * lda + k0 + c];
        }
        #pragma unroll
        for (int i = 0; i < 4; i++) {
            int e = tid + i * 256;
            int r = e >> 7, c = e & 127;             // 8 rows x 128 cols of B
            Bs[r][c] = B[(long long)(k0 + r) * ldb + col0 + c];
        }
        __syncthreads();

        #pragma unroll
        for (int kk = 0; kk < BK; kk++) {
            float ra[8], rb[8];
            #pragma unroll
            for (int i = 0; i < 8; i++) ra[i] = As[kk][ty * 8 + i];
            #pragma unroll
            for (int j = 0; j < 8; j++) rb[j] = Bs[kk][tx * 8 + j];
            #pragma unroll
            for (int i = 0; i < 8; i++)
                #pragma unroll
                for (int j = 0; j < 8; j++)
                    acc[i][j] = fmaf(ra[i], rb[j], acc[i][j]);
        }
        __syncthreads();
    }

    #pragma unroll
    for (int i = 0; i < 8; i++) {
        int r = row0 + ty * 8 + i;
        #pragma unroll
        for (int j = 0; j < 8; j++) {
            int c = col0 + tx * 8 + j;
            float v = acc[i][j];
            if (bias) v += bias[c];
            C[(long long)r * ldc + c] = v;
        }
    }
}

// C[q,n] = scale * sum_d A[q,d]*B[n,d]  (NT), then mask (int32, nonzero = masked -> NEG).
__global__ __launch_bounds__(256) void gemm_nt_masked(
    const float* __restrict__ A, const float* __restrict__ B,
    const int* __restrict__ mask, float* __restrict__ C,
    int M, int N, int K, int lda, int ldb, int ldc,
    long long sA, long long sB, long long sC, long long sMask,
    float scale)
{
    int b = blockIdx.z;
    A += (long long)b * sA; B += (long long)b * sB;
    C += (long long)b * sC; mask += (long long)b * sMask;

    __shared__ float As[BK][TILE];
    __shared__ float Bs[BK][TILE];

    int tid = threadIdx.x;
    int tx = tid & 15, ty = tid >> 4;
    int row0 = blockIdx.y * TILE;
    int col0 = blockIdx.x * TILE;

    float acc[8][8];
    #pragma unroll
    for (int i = 0; i < 8; i++)
        #pragma unroll
        for (int j = 0; j < 8; j++) acc[i][j] = 0.0f;

    for (int k0 = 0; k0 < K; k0 += BK) {
        #pragma unroll
        for (int i = 0; i < 4; i++) {
            int e = tid + i * 256;
            int r = e >> 3, c = e & 7;
            As[c][r] = A[(long long)(row0 + r) * lda + k0 + c];
        }
        #pragma unroll
        for (int i = 0; i < 4; i++) {
            int e = tid + i * 256;
            int r = e >> 3, c = e & 7;               // B is [N,K]: 128 N-rows x 8 k
            Bs[c][r] = B[(long long)(col0 + r) * ldb + k0 + c];
        }
        __syncthreads();

        #pragma unroll
        for (int kk = 0; kk < BK; kk++) {
            float ra[8], rb[8];
            #pragma unroll
            for (int i = 0; i < 8; i++) ra[i] = As[kk][ty * 8 + i];
            #pragma unroll
            for (int j = 0; j < 8; j++) rb[j] = Bs[kk][tx * 8 + j];
            #pragma unroll
            for (int i = 0; i < 8; i++)
                #pragma unroll
                for (int j = 0; j < 8; j++)
                    acc[i][j] = fmaf(ra[i], rb[j], acc[i][j]);
        }
        __syncthreads();
    }

    #pragma unroll
    for (int i = 0; i < 8; i++) {
        int r = row0 + ty * 8 + i;
        #pragma unroll
        for (int j = 0; j < 8; j++) {
            int c = col0 + tx * 8 + j;
            float v = acc[i][j] * scale;
            if (mask[(long long)r * N + c] != 0) v = NEGV;
            C[(long long)r * ldc + c] = v;
        }
    }
}

// In-place row softmax, one block per row.
__global__ __launch_bounds__(256) void softmax_rows(float* __restrict__ data, int n)
{
    float* row = data + (long long)blockIdx.x * n;
    __shared__ float red[256];
    int tid = threadIdx.x;

    float m = -CUDART_INF_F;
    for (int i = tid; i < n; i += 256) m = fmaxf(m, row[i]);
    red[tid] = m; __syncthreads();
    for (int s = 128; s > 0; s >>= 1) {
        if (tid < s) red[tid] = fmaxf(red[tid], red[tid + s]);
        __syncthreads();
    }
    m = red[0];
    __syncthreads();

    float sum = 0.0f;
    for (int i = tid; i < n; i += 256) {
        float e = __expf(row[i] - m);
        row[i] = e;
        sum += e;
    }
    red[tid] = sum; __syncthreads();
    for (int s = 128; s > 0; s >>= 1) {
        if (tid < s) red[tid] += red[tid + s];
        __syncthreads();
    }
    float inv = 1.0f / red[0];
    for (int i = tid; i < n; i += 256) row[i] *= inv;
}

extern "C" void kernel_launch(void* const* d_in, const int* in_sizes, int n_in,
                              void* d_out, int out_size)
{
    const float* X     = (const float*)d_in[0];
    const int*   mask  = (const int*)d_in[1];       // bool serialized as int32
    const float* W_qkv = (const float*)d_in[2];
    const float* b_qkv = (const float*)d_in[3];
    const float* W_out = (const float*)d_in[4];
    const float* b_out = (const float*)d_in[5];
    float*       out   = (float*)d_out;

    float *qkv, *scores, *ctx;
    cudaGetSymbolAddress((void**)&qkv,    g_qkv);
    cudaGetSymbolAddress((void**)&scores, g_scores);
    cudaGetSymbolAddress((void**)&ctx,    g_ctx);

    const int M  = BATCH * SEQ;          // 8192
    const float scale = 1.0f / 32.0f;    // 1/sqrt(1024)

    // 1) QKV = X @ W_qkv + b_qkv   [8192,1024]x[1024,3072]
    gemm_nn<<<dim3(DIM3 / TILE, M / TILE, 1), 256>>>(
        X, W_qkv, b_qkv, qkv, M, DIM3, DIM, DIM, DIM3, DIM3, 0, 0, 0);

    // 2) scores = mask ? NEG : (Q K^T) * scale   per batch
    gemm_nt_masked<<<dim3(SEQ / TILE, SEQ / TILE, BATCH), 256>>>(
        qkv /*Q*/, qkv + DIM /*K*/, mask, scores,
        SEQ, SEQ, DIM, DIM3, DIM3, SEQ,
        (long long)SEQ * DIM3, (long long)SEQ * DIM3,
        (long long)SEQ * SEQ, (long long)SEQ * SEQ, scale);

    // 3) softmax rows
    softmax_rows<<<BATCH * SEQ, 256>>>(scores, SEQ);

    // 4) ctx = attn @ V   per batch  [2048,2048]x[2048,1024]
    gemm_nn<<<dim3(DIM / TILE, SEQ / TILE, BATCH), 256>>>(
        scores, qkv + 2 * DIM /*V*/, nullptr, ctx,
        SEQ, DIM, SEQ, SEQ, DIM3, DIM,
        (long long)SEQ * SEQ, (long long)SEQ * DIM3, (long long)SEQ * DIM);

    // 5) out = ctx @ W_out + b_out  [8192,1024]x[1024,1024]
    gemm_nn<<<dim3(DIM / TILE, M / TILE, 1), 256>>>(
        ctx, W_out, b_out, out, M, DIM, DIM, DIM, DIM, DIM, 0, 0, 0);
}

// round 5
// speedup vs baseline: 2.0099x; 2.0099x over previous
#include <cuda_runtime.h>
#include <cuda_bf16.h>
#include <math_constants.h>
#include <cstdint>

#define BATCH 4
#define SEQ   2048
#define DIM   1024
#define DIM3  3072
#define NEGV  (-1e20f)

typedef __nv_bfloat16 bf16;

// ---------------- scratch (device globals; no allocation) ----------------
__device__ float g_qkv   [(size_t)BATCH * SEQ * DIM3];   // 96 MB (f32, for V transpose)
__device__ float g_scores[(size_t)BATCH * SEQ * SEQ];    // 64 MB

__device__ bf16 g_xh [(size_t)BATCH * SEQ * DIM];
__device__ bf16 g_xl [(size_t)BATCH * SEQ * DIM];
__device__ bf16 g_qkvh[(size_t)BATCH * SEQ * DIM3];
__device__ bf16 g_qkvl[(size_t)BATCH * SEQ * DIM3];
__device__ bf16 g_wqh[(size_t)DIM3 * DIM];
__device__ bf16 g_wql[(size_t)DIM3 * DIM];
__device__ bf16 g_vth[(size_t)BATCH * DIM * SEQ];
__device__ bf16 g_vtl[(size_t)BATCH * DIM * SEQ];
__device__ bf16 g_sh [(size_t)BATCH * SEQ * SEQ];
__device__ bf16 g_sl [(size_t)BATCH * SEQ * SEQ];
__device__ bf16 g_chh[(size_t)BATCH * SEQ * DIM];
__device__ bf16 g_chl[(size_t)BATCH * SEQ * DIM];
__device__ bf16 g_woh[(size_t)DIM * DIM];
__device__ bf16 g_wol[(size_t)DIM * DIM];

// ---------------- helpers ----------------
__device__ __forceinline__ uint32_t smem_u32(const void* p) {
    uint32_t a;
    asm("{ .reg .u64 t; cvta.to.shared.u64 t, %1; cvt.u32.u64 %0, t; }" : "=r"(a) : "l"(p));
    return a;
}
__device__ __forceinline__ uint32_t sw128(uint32_t o) { return o ^ ((o >> 3) & 0x70); }

#define CP_ASYNC16(dst, src) \
    asm volatile("cp.async.cg.shared.global [%0], [%1], 16;" :: "r"(dst), "l"(src))
#define CP_COMMIT() asm volatile("cp.async.commit_group;")
#define CP_WAIT1()  asm volatile("cp.async.wait_group 1;")
#define CP_WAIT0()  asm volatile("cp.async.wait_group 0;")

#define LDSM4(r0, r1, r2, r3, a) \
    asm volatile("ldmatrix.sync.aligned.m8n8.x4.shared.b16 {%0,%1,%2,%3}, [%4];" \
        : "=r"(r0), "=r"(r1), "=r"(r2), "=r"(r3) : "r"(a))

#define MMA16816(c, a, b) \
    asm volatile("mma.sync.aligned.m16n8k16.row.col.f32.bf16.bf16.f32 " \
        "{%0,%1,%2,%3}, {%4,%5,%6,%7}, {%8,%9}, {%0,%1,%2,%3};" \
        : "+f"((c)[0]), "+f"((c)[1]), "+f"((c)[2]), "+f"((c)[3]) \
        : "r"((a)[0]), "r"((a)[1]), "r"((a)[2]), "r"((a)[3]), "r"((b)[0]), "r"((b)[1]))

// ---------------- GEMM (mma.sync bf16, 3-pass split) ----------------
// C[m,n] = sum_k A[m,k]*B[n,k] (both K-major). Optional f32 out, bf16 hi/lo out,
// bias, mask(+scale). All dims multiples of 128 / K multiple of 64.
#define STG 65536            // per stage: AH 16K | AL 16K | BH 16K | BL 16K
#define OFF_AH 0
#define OFF_AL 16384
#define OFF_BH 32768
#define OFF_BL 49152
#define GEMM_SMEM (2 * STG)  // 128 KB

__device__ __forceinline__ void load_stage(
    uint32_t sbase,
    const bf16* __restrict__ Ah, const bf16* __restrict__ Al, int lda,
    const bf16* __restrict__ Bh, const bf16* __restrict__ Bl, int ldb,
    int k0, int tid)
{
#pragma unroll
    for (int it = 0; it < 4; it++) {
        int idx = tid + it * 256;
        int row = idx >> 3, ch = idx & 7;
        uint32_t d = sw128((uint32_t)row * 128 + ch * 16);
        size_t ea = (size_t)row * lda + k0 + ch * 8;
        size_t eb = (size_t)row * ldb + k0 + ch * 8;
        CP_ASYNC16(sbase + OFF_AH + d, Ah + ea);
        CP_ASYNC16(sbase + OFF_AL + d, Al + ea);
        CP_ASYNC16(sbase + OFF_BH + d, Bh + eb);
        CP_ASYNC16(sbase + OFF_BL + d, Bl + eb);
    }
    CP_COMMIT();
}

__global__ __launch_bounds__(256, 1) void gemm_mma(
    const bf16* __restrict__ Ah, const bf16* __restrict__ Al, long long sA, int lda,
    const bf16* __restrict__ Bh, const bf16* __restrict__ Bl, long long sB, int ldb,
    float* __restrict__ Cf, bf16* __restrict__ Chi, bf16* __restrict__ Clo,
    long long sC, int ldc,
    const float* __restrict__ bias,
    const int* __restrict__ mask, long long sM, float scale,
    int K)
{
    extern __shared__ char smem[];
    uint32_t sb = smem_u32(smem);
    int tid = threadIdx.x, w = tid >> 5, l = tid & 31;
    int wm = (w >> 2) * 64, wn = (w & 3) * 32;
    int b = blockIdx.z;
    Ah += (size_t)b * sA; Al += (size_t)b * sA;
    Bh += (size_t)b * sB; Bl += (size_t)b * sB;
    if (Cf)  Cf  += (size_t)b * sC;
    if (Chi) { Chi += (size_t)b * sC; Clo += (size_t)b * sC; }
    if (mask) mask += (size_t)b * sM;
    int row0 = blockIdx.y * 128, col0 = blockIdx.x * 128;

    const bf16* Ahr = Ah + (size_t)row0 * lda;
    const bf16* Alr = Al + (size_t)row0 * lda;
    const bf16* Bhr = Bh + (size_t)col0 * ldb;
    const bf16* Blr = Bl + (size_t)col0 * ldb;

    // ldmatrix swizzled offsets (per lane), constant across mainloop
    uint32_t aoff[4][4], boff[2][4];
#pragma unroll
    for (int mt = 0; mt < 4; mt++)
#pragma unroll
        for (int ks = 0; ks < 4; ks++)
            aoff[mt][ks] = sw128((uint32_t)(wm + mt * 16 + (l & 15)) * 128 + (l >> 4) * 16 + ks * 32);
#pragma unroll
    for (int g = 0; g < 2; g++)
#pragma unroll
        for (int ks = 0; ks < 4; ks++)
            boff[g][ks] = sw128((uint32_t)(wn + g * 16 + (l & 15)) * 128 + (l >> 4) * 16 + ks * 32);

    float acc[4][4][4];
#pragma unroll
    for (int mt = 0; mt < 4; mt++)
#pragma unroll
        for (int nt = 0; nt < 4; nt++)
#pragma unroll
            for (int r = 0; r < 4; r++) acc[mt][nt][r] = 0.0f;

    const int L = K >> 6;
    load_stage(sb, Ahr, Alr, lda, Bhr, Blr, ldb, 0, tid);

    for (int i = 0; i < L; i++) {
        if (i + 1 < L) {
            load_stage(sb + ((i + 1) & 1) * STG, Ahr, Alr, lda, Bhr, Blr, ldb, (i + 1) * 64, tid);
            CP_WAIT1();
        } else {
            CP_WAIT0();
        }
        __syncthreads();

        uint32_t base = sb + (i & 1) * STG;
#pragma unroll
        for (int ks = 0; ks < 4; ks++) {
            uint32_t ah[4][4], al[4][4], bh[4][2], bl[4][2];
#pragma unroll
            for (int mt = 0; mt < 4; mt++) {
                LDSM4(ah[mt][0], ah[mt][1], ah[mt][2], ah[mt][3], base + OFF_AH + aoff[mt][ks]);
                LDSM4(al[mt][0], al[mt][1], al[mt][2], al[mt][3], base + OFF_AL + aoff[mt][ks]);
            }
#pragma unroll
            for (int g = 0; g < 2; g++) {
                uint32_t q0, q1, q2, q3;
                LDSM4(q0, q1, q2, q3, base + OFF_BH + boff[g][ks]);
                bh[2 * g][0] = q0; bh[2 * g][1] = q2;
                bh[2 * g + 1][0] = q1; bh[2 * g + 1][1] = q3;
                LDSM4(q0, q1, q2, q3, base + OFF_BL + boff[g][ks]);
                bl[2 * g][0] = q0; bl[2 * g][1] = q2;
                bl[2 * g + 1][0] = q1; bl[2 * g + 1][1] = q3;
            }
#pragma unroll
            for (int mt = 0; mt < 4; mt++)
#pragma unroll
                for (int nt = 0; nt < 4; nt++) {
                    MMA16816(acc[mt][nt], ah[mt], bh[nt]);
                    MMA16816(acc[mt][nt], ah[mt], bl[nt]);
                    MMA16816(acc[mt][nt], al[mt], bh[nt]);
                }
        }
        __syncthreads();
    }

    // ---- epilogue ----
#pragma unroll
    for (int mt = 0; mt < 4; mt++) {
        int r0 = row0 + wm + mt * 16 + (l >> 2);
        int r1 = r0 + 8;
#pragma unroll
        for (int nt = 0; nt < 4; nt++) {
            int c = col0 + wn + nt * 8 + 2 * (l & 3);
            float2 v0 = make_float2(acc[mt][nt][0], acc[mt][nt][1]);
            float2 v1 = make_float2(acc[mt][nt][2], acc[mt][nt][3]);
            if (bias) {
                float2 bb = *(const float2*)(bias + c);
                v0.x += bb.x; v0.y += bb.y; v1.x += bb.x; v1.y += bb.y;
            }
            if (mask) {
                int2 m0 = *(const int2*)(mask + (size_t)r0 * ldc + c);
                int2 m1 = *(const int2*)(mask + (size_t)r1 * ldc + c);
                v0.x = m0.x ? NEGV : v0.x * scale;
                v0.y = m0.y ? NEGV : v0.y * scale;
                v1.x = m1.x ? NEGV : v1.x * scale;
                v1.y = m1.y ? NEGV : v1.y * scale;
            }
            if (Cf) {
                *(float2*)(Cf + (size_t)r0 * ldc + c) = v0;
                *(float2*)(Cf + (size_t)r1 * ldc + c) = v1;
            }
            if (Chi) {
                bf16 h0 = __float2bfloat16(v0.x), h1 = __float2bfloat16(v0.y);
                bf16 h2 = __float2bfloat16(v1.x), h3 = __float2bfloat16(v1.y);
                __nv_bfloat162 hp0(h0, h1), hp1(h2, h3);
                *(__nv_bfloat162*)(Chi + (size_t)r0 * ldc + c) = hp0;
                *(__nv_bfloat162*)(Chi + (size_t)r1 * ldc + c) = hp1;
                bf16 l0 = __float2bfloat16(v0.x - __bfloat162float(h0));
                bf16 l1 = __float2bfloat16(v0.y - __bfloat162float(h1));
                bf16 l2 = __float2bfloat16(v1.x - __bfloat162float(h2));
                bf16 l3 = __float2bfloat16(v1.y - __bfloat162float(h3));
                __nv_bfloat162 lp0(l0, l1), lp1(l2, l3);
                *(__nv_bfloat162*)(Clo + (size_t)r0 * ldc + c) = lp0;
                *(__nv_bfloat162*)(Clo + (size_t)r1 * ldc + c) = lp1;
            }
        }
    }
}

// ---------------- conversion kernels ----------------
__global__ __launch_bounds__(256) void split_kernel(
    const float4* __restrict__ in, bf16* __restrict__ oh, bf16* __restrict__ ol,
    long long n4)
{
    long long i = (long long)blockIdx.x * blockDim.x + threadIdx.x;
    if (i >= n4) return;
    float4 x = in[i];
    bf16 h0 = __float2bfloat16(x.x), h1 = __float2bfloat16(x.y);
    bf16 h2 = __float2bfloat16(x.z), h3 = __float2bfloat16(x.w);
    bf16 l0 = __float2bfloat16(x.x - __bfloat162float(h0));
    bf16 l1 = __float2bfloat16(x.y - __bfloat162float(h1));
    bf16 l2 = __float2bfloat16(x.z - __bfloat162float(h2));
    bf16 l3 = __float2bfloat16(x.w - __bfloat162float(h3));
    __nv_bfloat162 hp0(h0, h1), hp1(h2, h3), lp0(l0, l1), lp1(l2, l3);
    uint2 hu = make_uint2(*(uint32_t*)&hp0, *(uint32_t*)&hp1);
    uint2 lu = make_uint2(*(uint32_t*)&lp0, *(uint32_t*)&lp1);
    *(uint2*)(oh + i * 4) = hu;
    *(uint2*)(ol + i * 4) = lu;
}

// out[c*ldout + r] = in[r*ldin + c] (split into hi/lo), batched
__global__ __launch_bounds__(256) void splitT_kernel(
    const float* __restrict__ in, int ldin, long long sIn,
    bf16* __restrict__ oh, bf16* __restrict__ ol, int ldout, long long sOut)
{
    __shared__ float t[32][33];
    int b = blockIdx.z;
    in += (size_t)b * sIn; oh += (size_t)b * sOut; ol += (size_t)b * sOut;
    int c0 = blockIdx.x * 32, r0 = blockIdx.y * 32;
    int tx = threadIdx.x & 31, ty = threadIdx.x >> 5;   // 32 x 8
#pragma unroll
    for (int k = 0; k < 4; k++) {
        int r = r0 + ty + k * 8;
        t[ty + k * 8][tx] = in[(size_t)r * ldin + c0 + tx];
    }
    __syncthreads();
#pragma unroll
    for (int k = 0; k < 4; k++) {
        int c = c0 + ty + k * 8;
        float v = t[tx][ty + k * 8];
        bf16 h = __float2bfloat16(v);
        bf16 lo = __float2bfloat16(v - __bfloat162float(h));
        oh[(size_t)c * ldout + r0 + tx] = h;
        ol[(size_t)c * ldout + r0 + tx] = lo;
    }
}

// ---------------- softmax that emits bf16 hi/lo directly ----------------
__global__ __launch_bounds__(256) void softmax_split(
    const float* __restrict__ sc, bf16* __restrict__ sh, bf16* __restrict__ sl, int n)
{
    __shared__ float buf[SEQ];
    __shared__ float red[256];
    const float* row = sc + (size_t)blockIdx.x * n;
    bf16* oh = sh + (size_t)blockIdx.x * n;
    bf16* ol = sl + (size_t)blockIdx.x * n;
    int tid = threadIdx.x;

    float m = -CUDART_INF_F;
    for (int i = tid; i < n; i += 256) { float x = row[i]; buf[i] = x; m = fmaxf(m, x); }
    red[tid] = m; __syncthreads();
    for (int s = 128; s > 0; s >>= 1) {
        if (tid < s) red[tid] = fmaxf(red[tid], red[tid + s]);
        __syncthreads();
    }
    m = red[0];
    __syncthreads();

    float sum = 0.0f;
    for (int i = tid; i < n; i += 256) {
        float e = __expf(buf[i] - m);
        buf[i] = e;
        sum += e;
    }
    red[tid] = sum; __syncthreads();
    for (int s = 128; s > 0; s >>= 1) {
        if (tid < s) red[tid] += red[tid + s];
        __syncthreads();
    }
    float inv = 1.0f / red[0];
    for (int i = tid; i < n; i += 256) {
        float v = buf[i] * inv;
        bf16 h = __float2bfloat16(v);
        oh[i] = h;
        ol[i] = __float2bfloat16(v - __bfloat162float(h));
    }
}

// ---------------- host ----------------
extern "C" void kernel_launch(void* const* d_in, const int* in_sizes, int n_in,
                              void* d_out, int out_size)
{
    const float* X     = (const float*)d_in[0];
    const int*   mask  = (const int*)d_in[1];
    const float* W_qkv = (const float*)d_in[2];
    const float* b_qkv = (const float*)d_in[3];
    const float* W_out = (const float*)d_in[4];
    const float* b_out = (const float*)d_in[5];
    float*       out   = (float*)d_out;

    float *qkv, *scores;
    bf16 *xh, *xl, *qkvh, *qkvl, *wqh, *wql, *vth, *vtl, *sh, *sl, *ch, *cl, *woh, *wol;
    cudaGetSymbolAddress((void**)&qkv, g_qkv);
    cudaGetSymbolAddress((void**)&scores, g_scores);
    cudaGetSymbolAddress((void**)&xh, g_xh);   cudaGetSymbolAddress((void**)&xl, g_xl);
    cudaGetSymbolAddress((void**)&qkvh, g_qkvh); cudaGetSymbolAddress((void**)&qkvl, g_qkvl);
    cudaGetSymbolAddress((void**)&wqh, g_wqh); cudaGetSymbolAddress((void**)&wql, g_wql);
    cudaGetSymbolAddress((void**)&vth, g_vth); cudaGetSymbolAddress((void**)&vtl, g_vtl);
    cudaGetSymbolAddress((void**)&sh, g_sh);   cudaGetSymbolAddress((void**)&sl, g_sl);
    cudaGetSymbolAddress((void**)&ch, g_chh);  cudaGetSymbolAddress((void**)&cl, g_chl);
    cudaGetSymbolAddress((void**)&woh, g_woh); cudaGetSymbolAddress((void**)&wol, g_wol);

    cudaFuncSetAttribute(gemm_mma, cudaFuncAttributeMaxDynamicSharedMemorySize, GEMM_SMEM);

    const int M = BATCH * SEQ;            // 8192
    const float scale = 1.0f / 32.0f;

    // split X -> xh/xl
    {
        long long n4 = (long long)M * DIM / 4;
        split_kernel<<<(unsigned)((n4 + 255) / 256), 256>>>((const float4*)X, xh, xl, n4);
    }
    // transpose-split weights
    splitT_kernel<<<dim3(DIM3 / 32, DIM / 32, 1), 256>>>(W_qkv, DIM3, 0, wqh, wql, DIM, 0);
    splitT_kernel<<<dim3(DIM / 32, DIM / 32, 1), 256>>>(W_out, DIM, 0, woh, wol, DIM, 0);

    // 1) QKV = X @ Wqkv^T + b_qkv  -> f32 (for V) + bf16 hi/lo (Q,K direct use)
    gemm_mma<<<dim3(DIM3 / 128, M / 128, 1), 256, GEMM_SMEM>>>(
        xh, xl, 0, DIM, wqh, wql, 0, DIM,
        qkv, qkvh, qkvl, 0, DIM3, b_qkv, nullptr, 0, 1.0f, DIM);

    // transpose-split V slice -> vth/vtl  [b][d][s]
    splitT_kernel<<<dim3(DIM / 32, SEQ / 32, BATCH), 256>>>(
        qkv + 2 * DIM, DIM3, (long long)SEQ * DIM3, vth, vtl, SEQ, (long long)DIM * SEQ);

    // 2) scores = mask ? NEG : (Q K^T)/32   (f32 only)
    gemm_mma<<<dim3(SEQ / 128, SEQ / 128, BATCH), 256, GEMM_SMEM>>>(
        qkvh, qkvl, (long long)SEQ * DIM3, DIM3,
        qkvh + DIM, qkvl + DIM, (long long)SEQ * DIM3, DIM3,
        scores, nullptr, nullptr, (long long)SEQ * SEQ, SEQ,
        nullptr, mask, (long long)SEQ * SEQ, scale, DIM);

    // 3) softmax -> bf16 hi/lo attn directly
    softmax_split<<<BATCH * SEQ, 256>>>(scores, sh, sl, SEQ);

    // 4) ctx = attn @ V (via V^T)  -> bf16 hi/lo only
    gemm_mma<<<dim3(DIM / 128, SEQ / 128, BATCH), 256, GEMM_SMEM>>>(
        sh, sl, (long long)SEQ * SEQ, SEQ,
        vth, vtl, (long long)DIM * SEQ, SEQ,
        nullptr, ch, cl, (long long)SEQ * DIM, DIM,
        nullptr, nullptr, 0, 1.0f, SEQ);

    // 5) out = ctx @ Wout^T + b_out  (f32 only)
    gemm_mma<<<dim3(DIM / 128, M / 128, 1), 256, GEMM_SMEM>>>(
        ch, cl, 0, DIM, woh, wol, 0, DIM,
        out, nullptr, nullptr, 0, DIM, b_out, nullptr, 0, 1.0f, DIM);
}

// round 6
// speedup vs baseline: 4.2745x; 2.1267x over previous
#include <cuda_runtime.h>
#include <cuda_fp16.h>
#include <math_constants.h>
#include <cstdint>

#define BATCH 4
#define SEQ   2048
#define DIM   1024
#define DIM3  3072
#define NEGV  (-1e20f)

// ---------------- scratch (device globals; no allocation) ----------------
__device__ float g_qkv   [(size_t)BATCH * SEQ * DIM3];   // f32 QKV (V transpose source)
__device__ float g_scores[(size_t)BATCH * SEQ * SEQ];

__device__ __half g_xh  [(size_t)BATCH * SEQ * DIM];
__device__ __half g_qkvh[(size_t)BATCH * SEQ * DIM3];
__device__ __half g_qkvl[(size_t)BATCH * SEQ * DIM3];
__device__ __half g_wqh [(size_t)DIM3 * DIM];
__device__ __half g_wql [(size_t)DIM3 * DIM];
__device__ __half g_vth [(size_t)BATCH * DIM * SEQ];
__device__ __half g_vtl [(size_t)BATCH * DIM * SEQ];
__device__ __half g_sh  [(size_t)BATCH * SEQ * SEQ];
__device__ __half g_ch  [(size_t)BATCH * SEQ * DIM];
__device__ __half g_woh [(size_t)DIM * DIM];
__device__ __half g_wol [(size_t)DIM * DIM];

// ---------------- helpers ----------------
__device__ __forceinline__ uint32_t smem_u32(const void* p) {
    uint32_t a;
    asm("{ .reg .u64 t; cvta.to.shared.u64 t, %1; cvt.u32.u64 %0, t; }" : "=r"(a) : "l"(p));
    return a;
}
__device__ __forceinline__ uint32_t sw128(uint32_t o) { return o ^ ((o >> 3) & 0x70); }

#define CP_ASYNC16(dst, src) \
    asm volatile("cp.async.cg.shared.global [%0], [%1], 16;" :: "r"(dst), "l"(src))
#define CP_COMMIT() asm volatile("cp.async.commit_group;")
#define CP_WAIT1()  asm volatile("cp.async.wait_group 1;")
#define CP_WAIT0()  asm volatile("cp.async.wait_group 0;")

#define LDSM4(r0, r1, r2, r3, a) \
    asm volatile("ldmatrix.sync.aligned.m8n8.x4.shared.b16 {%0,%1,%2,%3}, [%4];" \
        : "=r"(r0), "=r"(r1), "=r"(r2), "=r"(r3) : "r"(a))

#define MMA16816(c, a, b) \
    asm volatile("mma.sync.aligned.m16n8k16.row.col.f32.f16.f16.f32 " \
        "{%0,%1,%2,%3}, {%4,%5,%6,%7}, {%8,%9}, {%0,%1,%2,%3};" \
        : "+f"((c)[0]), "+f"((c)[1]), "+f"((c)[2]), "+f"((c)[3]) \
        : "r"((a)[0]), "r"((a)[1]), "r"((a)[2]), "r"((a)[3]), "r"((b)[0]), "r"((b)[1]))

// ---------------- GEMM: C[m,n] = sum_k A[m,k]*B[n,k] (K-major both) ----------------
// 2-pass fp16 split: A_hi * (B_hi + B_lo). 128x128 tile, BK=64, 3-stage cp.async.
#define OFF_AH 0
#define OFF_BH 16384
#define OFF_BL 32768
#define STG    49152
#define GEMM_SMEM (3 * STG)   // 144 KB

__device__ __forceinline__ void load_stage(
    uint32_t sbase,
    const __half* __restrict__ Ah, int lda,
    const __half* __restrict__ Bh, const __half* __restrict__ Bl, int ldb,
    int k0, int tid)
{
#pragma unroll
    for (int it = 0; it < 4; it++) {
        int idx = tid + it * 256;
        int row = idx >> 3, ch = idx & 7;
        uint32_t d = sw128((uint32_t)row * 128 + ch * 16);
        CP_ASYNC16(sbase + OFF_AH + d, Ah + (size_t)row * lda + k0 + ch * 8);
    }
#pragma unroll
    for (int it = 0; it < 4; it++) {
        int idx = tid + it * 256;
        int row = idx >> 3, ch = idx & 7;
        uint32_t d = sw128((uint32_t)row * 128 + ch * 16);
        size_t eb = (size_t)row * ldb + k0 + ch * 8;
        CP_ASYNC16(sbase + OFF_BH + d, Bh + eb);
        CP_ASYNC16(sbase + OFF_BL + d, Bl + eb);
    }
    CP_COMMIT();
}

__global__ __launch_bounds__(256, 1) void gemm_mma(
    const __half* __restrict__ Ah, long long sA, int lda,
    const __half* __restrict__ Bh, const __half* __restrict__ Bl, long long sB, int ldb,
    float* __restrict__ Cf, __half* __restrict__ Chi, __half* __restrict__ Clo,
    long long sC, int ldc,
    const float* __restrict__ bias,
    const int* __restrict__ mask, long long sM, float scale,
    int K)
{
    extern __shared__ char smem[];
    uint32_t sb = smem_u32(smem);
    int tid = threadIdx.x, w = tid >> 5, l = tid & 31;
    int wm = (w >> 2) * 64, wn = (w & 3) * 32;
    int b = blockIdx.z;
    Ah += (size_t)b * sA;
    Bh += (size_t)b * sB; Bl += (size_t)b * sB;
    if (Cf)  Cf  += (size_t)b * sC;
    if (Chi) Chi += (size_t)b * sC;
    if (Clo) Clo += (size_t)b * sC;
    if (mask) mask += (size_t)b * sM;
    int row0 = blockIdx.y * 128, col0 = blockIdx.x * 128;

    const __half* Ahr = Ah + (size_t)row0 * lda;
    const __half* Bhr = Bh + (size_t)col0 * ldb;
    const __half* Blr = Bl + (size_t)col0 * ldb;

    uint32_t aoff[4][4], boff[2][4];
#pragma unroll
    for (int mt = 0; mt < 4; mt++)
#pragma unroll
        for (int ks = 0; ks < 4; ks++)
            aoff[mt][ks] = sw128((uint32_t)(wm + mt * 16 + (l & 15)) * 128 + (l >> 4) * 16 + ks * 32);
#pragma unroll
    for (int g = 0; g < 2; g++)
#pragma unroll
        for (int ks = 0; ks < 4; ks++)
            boff[g][ks] = sw128((uint32_t)(wn + g * 16 + (l & 15)) * 128 + (l >> 4) * 16 + ks * 32);

    float acc[4][4][4];
#pragma unroll
    for (int mt = 0; mt < 4; mt++)
#pragma unroll
        for (int nt = 0; nt < 4; nt++)
#pragma unroll
            for (int r = 0; r < 4; r++) acc[mt][nt][r] = 0.0f;

    const int L = K >> 6;
    load_stage(sb + 0 * STG, Ahr, lda, Bhr, Blr, ldb, 0, tid);
    load_stage(sb + 1 * STG, Ahr, lda, Bhr, Blr, ldb, 64, tid);

    for (int i = 0; i < L; i++) {
        CP_WAIT1();                 // stage i complete
        __syncthreads();            // visible to all; all done reading stage (i+2)%3
        if (i + 2 < L)
            load_stage(sb + ((i + 2) % 3) * STG, Ahr, lda, Bhr, Blr, ldb, (i + 2) * 64, tid);

        uint32_t base = sb + (i % 3) * STG;
#pragma unroll
        for (int ks = 0; ks < 4; ks++) {
            uint32_t a[4][4], bh[4][2], bl[4][2];
#pragma unroll
            for (int mt = 0; mt < 4; mt++)
                LDSM4(a[mt][0], a[mt][1], a[mt][2], a[mt][3], base + OFF_AH + aoff[mt][ks]);
#pragma unroll
            for (int g = 0; g < 2; g++) {
                uint32_t q0, q1, q2, q3;
                LDSM4(q0, q1, q2, q3, base + OFF_BH + boff[g][ks]);
                bh[2 * g][0] = q0; bh[2 * g][1] = q2;
                bh[2 * g + 1][0] = q1; bh[2 * g + 1][1] = q3;
                LDSM4(q0, q1, q2, q3, base + OFF_BL + boff[g][ks]);
                bl[2 * g][0] = q0; bl[2 * g][1] = q2;
                bl[2 * g + 1][0] = q1; bl[2 * g + 1][1] = q3;
            }
            // pass-major: 16 independent accs between same-acc reuses
#pragma unroll
            for (int mt = 0; mt < 4; mt++)
#pragma unroll
                for (int nt = 0; nt < 4; nt++)
                    MMA16816(acc[mt][nt], a[mt], bh[nt]);
#pragma unroll
            for (int mt = 0; mt < 4; mt++)
#pragma unroll
                for (int nt = 0; nt < 4; nt++)
                    MMA16816(acc[mt][nt], a[mt], bl[nt]);
        }
    }

    // ---- epilogue ----
#pragma unroll
    for (int mt = 0; mt < 4; mt++) {
        int r0 = row0 + wm + mt * 16 + (l >> 2);
        int r1 = r0 + 8;
#pragma unroll
        for (int nt = 0; nt < 4; nt++) {
            int c = col0 + wn + nt * 8 + 2 * (l & 3);
            float2 v0 = make_float2(acc[mt][nt][0], acc[mt][nt][1]);
            float2 v1 = make_float2(acc[mt][nt][2], acc[mt][nt][3]);
            if (bias) {
                float2 bb = *(const float2*)(bias + c);
                v0.x += bb.x; v0.y += bb.y; v1.x += bb.x; v1.y += bb.y;
            }
            if (mask) {
                int2 m0 = *(const int2*)(mask + (size_t)r0 * ldc + c);
                int2 m1 = *(const int2*)(mask + (size_t)r1 * ldc + c);
                v0.x = m0.x ? NEGV : v0.x * scale;
                v0.y = m0.y ? NEGV : v0.y * scale;
                v1.x = m1.x ? NEGV : v1.x * scale;
                v1.y = m1.y ? NEGV : v1.y * scale;
            }
            if (Cf) {
                *(float2*)(Cf + (size_t)r0 * ldc + c) = v0;
                *(float2*)(Cf + (size_t)r1 * ldc + c) = v1;
            }
            if (Chi) {
                __half h0 = __float2half(v0.x), h1 = __float2half(v0.y);
                __half h2 = __float2half(v1.x), h3 = __float2half(v1.y);
                *(__half2*)(Chi + (size_t)r0 * ldc + c) = __halves2half2(h0, h1);
                *(__half2*)(Chi + (size_t)r1 * ldc + c) = __halves2half2(h2, h3);
                if (Clo) {
                    __half l0 = __float2half(v0.x - __half2float(h0));
                    __half l1 = __float2half(v0.y - __half2float(h1));
                    __half l2 = __float2half(v1.x - __half2float(h2));
                    __half l3 = __float2half(v1.y - __half2float(h3));
                    *(__half2*)(Clo + (size_t)r0 * ldc + c) = __halves2half2(l0, l1);
                    *(__half2*)(Clo + (size_t)r1 * ldc + c) = __halves2half2(l2, l3);
                }
            }
        }
    }
}

// ---------------- conversions ----------------
__global__ __launch_bounds__(256) void split_hi(
    const float4* __restrict__ in, __half* __restrict__ oh, long long n4)
{
    long long i = (long long)blockIdx.x * blockDim.x + threadIdx.x;
    if (i >= n4) return;
    float4 x = in[i];
    __half2 h0 = __floats2half2_rn(x.x, x.y);
    __half2 h1 = __floats2half2_rn(x.z, x.w);
    *(uint2*)(oh + i * 4) = make_uint2(*(uint32_t*)&h0, *(uint32_t*)&h1);
}

// out[c*ldout + r] = in[r*ldin + c] split hi/lo, batched
__global__ __launch_bounds__(256) void splitT_kernel(
    const float* __restrict__ in, int ldin, long long sIn,
    __half* __restrict__ oh, __half* __restrict__ ol, int ldout, long long sOut)
{
    __shared__ float t[32][33];
    int b = blockIdx.z;
    in += (size_t)b * sIn; oh += (size_t)b * sOut; ol += (size_t)b * sOut;
    int c0 = blockIdx.x * 32, r0 = blockIdx.y * 32;
    int tx = threadIdx.x & 31, ty = threadIdx.x >> 5;
#pragma unroll
    for (int k = 0; k < 4; k++) {
        int r = r0 + ty + k * 8;
        t[ty + k * 8][tx] = in[(size_t)r * ldin + c0 + tx];
    }
    __syncthreads();
#pragma unroll
    for (int k = 0; k < 4; k++) {
        int c = c0 + ty + k * 8;
        float v = t[tx][ty + k * 8];
        __half h = __float2half(v);
        oh[(size_t)c * ldout + r0 + tx] = h;
        ol[(size_t)c * ldout + r0 + tx] = __float2half(v - __half2float(h));
    }
}

// ---------------- softmax -> fp16 hi ----------------
__global__ __launch_bounds__(256) void softmax_h(
    const float* __restrict__ sc, __half* __restrict__ sh, int n)
{
    __shared__ float buf[SEQ];
    __shared__ float red[256];
    const float* row = sc + (size_t)blockIdx.x * n;
    __half* oh = sh + (size_t)blockIdx.x * n;
    int tid = threadIdx.x;

    float m = -CUDART_INF_F;
    for (int i = tid; i < n; i += 256) { float x = row[i]; buf[i] = x; m = fmaxf(m, x); }
    red[tid] = m; __syncthreads();
    for (int s = 128; s > 0; s >>= 1) {
        if (tid < s) red[tid] = fmaxf(red[tid], red[tid + s]);
        __syncthreads();
    }
    m = red[0];
    __syncthreads();

    float sum = 0.0f;
    for (int i = tid; i < n; i += 256) {
        float e = __expf(buf[i] - m);
        buf[i] = e; sum += e;
    }
    red[tid] = sum; __syncthreads();
    for (int s = 128; s > 0; s >>= 1) {
        if (tid < s) red[tid] += red[tid + s];
        __syncthreads();
    }
    float inv = 1.0f / red[0];
    for (int i = tid; i < n; i += 256) oh[i] = __float2half(buf[i] * inv);
}

// ---------------- host ----------------
extern "C" void kernel_launch(void* const* d_in, const int* in_sizes, int n_in,
                              void* d_out, int out_size)
{
    const float* X     = (const float*)d_in[0];
    const int*   mask  = (const int*)d_in[1];
    const float* W_qkv = (const float*)d_in[2];
    const float* b_qkv = (const float*)d_in[3];
    const float* W_out = (const float*)d_in[4];
    const float* b_out = (const float*)d_in[5];
    float*       out   = (float*)d_out;

    float *qkv, *scores;
    __half *xh, *qkvh, *qkvl, *wqh, *wql, *vth, *vtl, *sh, *ch, *woh, *wol;
    cudaGetSymbolAddress((void**)&qkv, g_qkv);
    cudaGetSymbolAddress((void**)&scores, g_scores);
    cudaGetSymbolAddress((void**)&xh, g_xh);
    cudaGetSymbolAddress((void**)&qkvh, g_qkvh); cudaGetSymbolAddress((void**)&qkvl, g_qkvl);
    cudaGetSymbolAddress((void**)&wqh, g_wqh); cudaGetSymbolAddress((void**)&wql, g_wql);
    cudaGetSymbolAddress((void**)&vth, g_vth); cudaGetSymbolAddress((void**)&vtl, g_vtl);
    cudaGetSymbolAddress((void**)&sh, g_sh);
    cudaGetSymbolAddress((void**)&ch, g_ch);
    cudaGetSymbolAddress((void**)&woh, g_woh); cudaGetSymbolAddress((void**)&wol, g_wol);

    cudaFuncSetAttribute(gemm_mma, cudaFuncAttributeMaxDynamicSharedMemorySize, GEMM_SMEM);

    const int M = BATCH * SEQ;
    const float scale = 1.0f / 32.0f;

    {   // X -> hi fp16
        long long n4 = (long long)M * DIM / 4;
        split_hi<<<(unsigned)((n4 + 255) / 256), 256>>>((const float4*)X, xh, n4);
    }
    splitT_kernel<<<dim3(DIM3 / 32, DIM / 32, 1), 256>>>(W_qkv, DIM3, 0, wqh, wql, DIM, 0);
    splitT_kernel<<<dim3(DIM / 32, DIM / 32, 1), 256>>>(W_out, DIM, 0, woh, wol, DIM, 0);

    // 1) QKV = X @ Wqkv^T + b  -> f32 + fp16 hi/lo
    gemm_mma<<<dim3(DIM3 / 128, M / 128, 1), 256, GEMM_SMEM>>>(
        xh, 0, DIM, wqh, wql, 0, DIM,
        qkv, qkvh, qkvl, 0, DIM3, b_qkv, nullptr, 0, 1.0f, DIM);

    // V^T hi/lo
    splitT_kernel<<<dim3(DIM / 32, SEQ / 32, BATCH), 256>>>(
        qkv + 2 * DIM, DIM3, (long long)SEQ * DIM3, vth, vtl, SEQ, (long long)DIM * SEQ);

    // 2) scores = mask ? NEG : (Q K^T)/32
    gemm_mma<<<dim3(SEQ / 128, SEQ / 128, BATCH), 256, GEMM_SMEM>>>(
        qkvh, (long long)SEQ * DIM3, DIM3,
        qkvh + DIM, qkvl + DIM, (long long)SEQ * DIM3, DIM3,
        scores, nullptr, nullptr, (long long)SEQ * SEQ, SEQ,
        nullptr, mask, (long long)SEQ * SEQ, scale, DIM);

    // 3) softmax -> fp16 hi
    softmax_h<<<BATCH * SEQ, 256>>>(scores, sh, SEQ);

    // 4) ctx = attn @ V  -> fp16 hi only
    gemm_mma<<<dim3(DIM / 128, SEQ / 128, BATCH), 256, GEMM_SMEM>>>(
        sh, (long long)SEQ * SEQ, SEQ,
        vth, vtl, (long long)DIM * SEQ, SEQ,
        nullptr, ch, nullptr, (long long)SEQ * DIM, DIM,
        nullptr, nullptr, 0, 1.0f, SEQ);

    // 5) out = ctx @ Wout^T + b
    gemm_mma<<<dim3(DIM / 128, M / 128, 1), 256, GEMM_SMEM>>>(
        ch, 0, DIM, woh, wol, 0, DIM,
        out, nullptr, nullptr, 0, DIM, b_out, nullptr, 0, 1.0f, DIM);
}